// round 10
// baseline (speedup 1.0000x reference)
#include <cuda_runtime.h>
#include <cuda_bf16.h>
#include <cuda_fp16.h>
#include <cstdint>
#include <cstddef>

#define NPTS 8192
#define DIM  1024
typedef __nv_bfloat16 bf16;

#define AL __align__(256)
__device__ AL bf16 g_ph[(size_t)NPTS * DIM], g_pl[(size_t)NPTS * DIM];
__device__ AL bf16 g_rh[(size_t)NPTS * DIM], g_rl[(size_t)NPTS * DIM];
__device__ AL bf16 g_Whh[(size_t)DIM * DIM], g_Whl[(size_t)DIM * DIM];
__device__ AL bf16 g_Wlh[(size_t)DIM * DIM], g_Wll[(size_t)DIM * DIM];
__device__ AL bf16 g_Wgh[(size_t)DIM * DIM], g_Wgl[(size_t)DIM * DIM];
__device__ AL bf16 g_Qh[(size_t)NPTS * DIM], g_Ql[(size_t)NPTS * DIM];
__device__ AL bf16 g_Kh[(size_t)NPTS * DIM], g_Kl[(size_t)NPTS * DIM];
__device__ AL float g_V[(size_t)NPTS * DIM];
__device__ AL __half g_VT[(size_t)DIM * NPTS];
__device__ AL __half g_E[(size_t)NPTS * NPTS];
__device__ AL float g_M[64 * NPTS];
__device__ AL float g_S[64 * NPTS];
__device__ AL float g_sc[64 * NPTS];

__device__ __forceinline__ uint32_t smem_u32(const void* p) {
    uint32_t a;
    asm("{ .reg .u64 t; cvta.to.shared.u64 t, %1; cvt.u32.u64 %0, t; }" : "=r"(a) : "l"(p));
    return a;
}
__device__ __forceinline__ void cp16(uint32_t dst, const void* src) {
    asm volatile("cp.async.cg.shared.global [%0], [%1], 16;"
                 :: "r"(dst), "l"(__cvta_generic_to_global(src)) : "memory");
}
__device__ __forceinline__ void ldmx4(uint32_t* r, uint32_t addr) {
    asm volatile("ldmatrix.sync.aligned.m8n8.x4.shared.b16 {%0,%1,%2,%3}, [%4];"
                 : "=r"(r[0]), "=r"(r[1]), "=r"(r[2]), "=r"(r[3]) : "r"(addr));
}
__device__ __forceinline__ void mma_bf(float* c, const uint32_t* a, const uint32_t* b) {
    asm volatile("mma.sync.aligned.m16n8k16.row.col.f32.bf16.bf16.f32 "
                 "{%0,%1,%2,%3}, {%4,%5,%6,%7}, {%8,%9}, {%0,%1,%2,%3};"
                 : "+f"(c[0]), "+f"(c[1]), "+f"(c[2]), "+f"(c[3])
                 : "r"(a[0]), "r"(a[1]), "r"(a[2]), "r"(a[3]), "r"(b[0]), "r"(b[1]));
}
__device__ __forceinline__ void mma_hf(float* c, const uint32_t* a, const uint32_t* b) {
    asm volatile("mma.sync.aligned.m16n8k16.row.col.f32.f16.f16.f32 "
                 "{%0,%1,%2,%3}, {%4,%5,%6,%7}, {%8,%9}, {%0,%1,%2,%3};"
                 : "+f"(c[0]), "+f"(c[1]), "+f"(c[2]), "+f"(c[3])
                 : "r"(a[0]), "r"(a[1]), "r"(a[2]), "r"(a[3]), "r"(b[0]), "r"(b[1]));
}

// Tile: 128x128, BK=32 (64B rows, 16B-chunk swizzle), 3-stage cp.async pipeline.
#define BK 32
#define NSTG 3
#define GSMEM3 (3u * 32768u)
#define GSMEM1 (3u * 16384u)

__device__ __forceinline__ uint32_t swz(int row, int chunk) {
    return (uint32_t)(row * 64 + ((chunk ^ ((row >> 1) & 3)) << 4));
}

// MODE 0: bias+fp32 | 1: bias+bf16 hi/lo | 2: tile-softmax (fp16 E + M/S partials)
// MODE 3: residual fp32.  NPROD 3: hh+hl+lh | 1: hh.  HF: fp16 operands (PV).
template <int MODE, int NPROD, int HF>
__global__ __launch_bounds__(256, 2) void gemm_mma(
    const bf16* __restrict__ Ahi, const bf16* __restrict__ Alo,
    const bf16* __restrict__ Bhi, const bf16* __restrict__ Blo,
    int Kd, int ldC, const float* __restrict__ bias, const float* __restrict__ P0,
    float* __restrict__ Cf, bf16* __restrict__ Chi, bf16* __restrict__ Clo,
    float* __restrict__ Mg, float* __restrict__ Sg)
{
    constexpr uint32_t STGB   = (NPROD == 1) ? 16384u : 32768u;
    constexpr uint32_t OF_ALO = 8192u;
    constexpr uint32_t OF_BHI = (NPROD == 1) ? 8192u : 16384u;
    constexpr uint32_t OF_BLO = 24576u;

    extern __shared__ char smraw[];
    const uint32_t sm0 = smem_u32(smraw);
    const int tid = threadIdx.x, lane = tid & 31, warp = tid >> 5;
    const int wm = warp >> 1, wn = warp & 1;
    const int row0 = blockIdx.y * 128, col0 = blockIdx.x * 128;

    uint32_t aoff[2][2], boff[4][2];
#pragma unroll
    for (int mi = 0; mi < 2; mi++)
#pragma unroll
        for (int ks = 0; ks < 2; ks++) {
            const int r = wm * 32 + mi * 16 + (lane & 15);
            aoff[mi][ks] = swz(r, ks * 2 + (lane >> 4));
        }
#pragma unroll
    for (int np = 0; np < 4; np++)
#pragma unroll
        for (int ks = 0; ks < 2; ks++) {
            const int r = wn * 64 + np * 16 + (lane & 7) + ((lane >> 4) & 1) * 8;
            boff[np][ks] = swz(r, ks * 2 + ((lane >> 3) & 1));
        }

    const int ldr = tid >> 2, ldc = tid & 3;

    auto load_stage = [&](int kb, int st) {
        const int k0 = kb * BK;
        const uint32_t s = sm0 + (uint32_t)st * STGB;
#pragma unroll
        for (int i = 0; i < 2; i++) {
            const int row = ldr + i * 64;
            const uint32_t d = swz(row, ldc);
            const size_t ga = (size_t)(row0 + row) * Kd + k0 + ldc * 8;
            const size_t gb = (size_t)(col0 + row) * Kd + k0 + ldc * 8;
            cp16(s + d, Ahi + ga);
            cp16(s + OF_BHI + d, Bhi + gb);
            if (NPROD == 3) {
                cp16(s + OF_ALO + d, Alo + ga);
                cp16(s + OF_BLO + d, Blo + gb);
            }
        }
    };

    float acc[2][8][4];
#pragma unroll
    for (int mi = 0; mi < 2; mi++)
#pragma unroll
        for (int ni = 0; ni < 8; ni++)
#pragma unroll
            for (int q = 0; q < 4; q++) acc[mi][ni][q] = 0.f;

    const int nkb = Kd / BK;
    load_stage(0, 0);
    asm volatile("cp.async.commit_group;" ::: "memory");
    load_stage(1, 1);
    asm volatile("cp.async.commit_group;" ::: "memory");

    int st = 0, pf = 2;
    for (int kb = 0; kb < nkb; kb++) {
        asm volatile("cp.async.wait_group 1;" ::: "memory");
        __syncthreads();
        if (kb + 2 < nkb) load_stage(kb + 2, pf);
        asm volatile("cp.async.commit_group;" ::: "memory");

        const uint32_t s = sm0 + (uint32_t)st * STGB;
#pragma unroll
        for (int ks = 0; ks < 2; ks++) {
            uint32_t ah[2][4], al[2][4], bh[8][2], bl[8][2];
#pragma unroll
            for (int mi = 0; mi < 2; mi++) {
                ldmx4(ah[mi], s + aoff[mi][ks]);
                if (NPROD == 3) ldmx4(al[mi], s + OF_ALO + aoff[mi][ks]);
            }
#pragma unroll
            for (int np = 0; np < 4; np++) {
                uint32_t t[4];
                ldmx4(t, s + OF_BHI + boff[np][ks]);
                bh[np*2][0] = t[0]; bh[np*2][1] = t[1];
                bh[np*2+1][0] = t[2]; bh[np*2+1][1] = t[3];
                if (NPROD == 3) {
                    ldmx4(t, s + OF_BLO + boff[np][ks]);
                    bl[np*2][0] = t[0]; bl[np*2][1] = t[1];
                    bl[np*2+1][0] = t[2]; bl[np*2+1][1] = t[3];
                }
            }
#pragma unroll
            for (int mi = 0; mi < 2; mi++)
#pragma unroll
                for (int ni = 0; ni < 8; ni++) {
                    if (HF) mma_hf(acc[mi][ni], ah[mi], bh[ni]);
                    else    mma_bf(acc[mi][ni], ah[mi], bh[ni]);
                }
            if (NPROD == 3) {
#pragma unroll
                for (int mi = 0; mi < 2; mi++)
#pragma unroll
                    for (int ni = 0; ni < 8; ni++)
                        mma_bf(acc[mi][ni], ah[mi], bl[ni]);
#pragma unroll
                for (int mi = 0; mi < 2; mi++)
#pragma unroll
                    for (int ni = 0; ni < 8; ni++)
                        mma_bf(acc[mi][ni], al[mi], bh[ni]);
            }
        }
        st = (st == NSTG - 1) ? 0 : st + 1;
        pf = (pf == NSTG - 1) ? 0 : pf + 1;
    }

    if (MODE == 2) {
        // Tile-local softmax epilogue. Reuse stage smem (mainloop done).
        __syncthreads();
        float* Msm  = (float*)smraw;            // [4][128]
        float* Mfin = (float*)(smraw + 2048);   // [128]
        float* Ssm  = (float*)(smraw + 2560);   // [4][128]
        // 1) per-column max over this CTA's 128 rows
#pragma unroll
        for (int ni = 0; ni < 8; ni++)
#pragma unroll
            for (int cc = 0; cc < 2; cc++) {
                float v = fmaxf(fmaxf(acc[0][ni][cc], acc[0][ni][2 + cc]),
                                fmaxf(acc[1][ni][cc], acc[1][ni][2 + cc]));
                v = fmaxf(v, __shfl_xor_sync(0xffffffffu, v, 4));
                v = fmaxf(v, __shfl_xor_sync(0xffffffffu, v, 8));
                v = fmaxf(v, __shfl_xor_sync(0xffffffffu, v, 16));
                if (lane < 4) Msm[wm * 128 + wn * 64 + ni * 8 + lane * 2 + cc] = v;
            }
        __syncthreads();
        if (tid < 128) {
            float m = fmaxf(fmaxf(Msm[tid], Msm[128 + tid]),
                            fmaxf(Msm[256 + tid], Msm[384 + tid]));
            Mfin[tid] = m;
        }
        __syncthreads();
        // 2) e = exp(s - Mtile): write fp16 E, accumulate column sums
        __half* Eo = (__half*)Chi;
        float ss[8][2];
#pragma unroll
        for (int ni = 0; ni < 8; ni++) { ss[ni][0] = 0.f; ss[ni][1] = 0.f; }
#pragma unroll
        for (int mi = 0; mi < 2; mi++)
#pragma unroll
            for (int ni = 0; ni < 8; ni++) {
                const int cl = wn * 64 + ni * 8 + (lane & 3) * 2;
                const int c  = col0 + cl;
                const float M0 = Mfin[cl], M1 = Mfin[cl + 1];
#pragma unroll
                for (int h = 0; h < 2; h++) {
                    const int m = row0 + wm * 32 + mi * 16 + (lane >> 2) + h * 8;
                    float e0 = __expf(acc[mi][ni][2 * h]     - M0);
                    float e1 = __expf(acc[mi][ni][2 * h + 1] - M1);
                    *(__half2*)&Eo[(size_t)m * ldC + c] = __floats2half2_rn(e0, e1);
                    ss[ni][0] += e0; ss[ni][1] += e1;
                }
            }
#pragma unroll
        for (int ni = 0; ni < 8; ni++)
#pragma unroll
            for (int cc = 0; cc < 2; cc++) {
                float v = ss[ni][cc];
                v += __shfl_xor_sync(0xffffffffu, v, 4);
                v += __shfl_xor_sync(0xffffffffu, v, 8);
                v += __shfl_xor_sync(0xffffffffu, v, 16);
                if (lane < 4) Ssm[wm * 128 + wn * 64 + ni * 8 + lane * 2 + cc] = v;
            }
        __syncthreads();
        if (tid < 128) {
            float s = Ssm[tid] + Ssm[128 + tid] + Ssm[256 + tid] + Ssm[384 + tid];
            Mg[(size_t)blockIdx.y * ldC + col0 + tid] = Mfin[tid];
            Sg[(size_t)blockIdx.y * ldC + col0 + tid] = s;
        }
        return;
    }

#pragma unroll
    for (int mi = 0; mi < 2; mi++)
#pragma unroll
        for (int ni = 0; ni < 8; ni++) {
            const int m0 = row0 + wm * 32 + mi * 16 + (lane >> 2);
            const int c  = col0 + wn * 64 + ni * 8 + (lane & 3) * 2;
#pragma unroll
            for (int h = 0; h < 2; h++) {
                const int m = m0 + h * 8;
                float v0 = acc[mi][ni][2 * h], v1 = acc[mi][ni][2 * h + 1];
                if (MODE == 0) {
                    float2* dst = (float2*)&Cf[(size_t)m * ldC + c];
                    *dst = make_float2(v0 + bias[c], v1 + bias[c + 1]);
                } else if (MODE == 3) {
                    const float2 pp = *(const float2*)&P0[(size_t)m * ldC + c];
                    float2* dst = (float2*)&Cf[(size_t)m * ldC + c];
                    *dst = make_float2(v0 + pp.x, v1 + pp.y);
                } else {  // MODE 1: bias + bf16 hi/lo split
                    v0 += bias[c]; v1 += bias[c + 1];
                    bf16 h0 = __float2bfloat16(v0), h1 = __float2bfloat16(v1);
                    *(__nv_bfloat162*)&Chi[(size_t)m * ldC + c] = __nv_bfloat162(h0, h1);
                    *(__nv_bfloat162*)&Clo[(size_t)m * ldC + c] =
                        __nv_bfloat162(__float2bfloat16(v0 - __bfloat162float(h0)),
                                       __float2bfloat16(v1 - __bfloat162float(h1)));
                }
            }
        }
}

__global__ __launch_bounds__(256) void split_kernel(
    const float4* __restrict__ x, __nv_bfloat162* __restrict__ hi,
    __nv_bfloat162* __restrict__ lo, int n4)
{
    int i = blockIdx.x * 256 + threadIdx.x;
    if (i >= n4) return;
    float4 v = x[i];
    bf16 h0 = __float2bfloat16(v.x), h1 = __float2bfloat16(v.y);
    bf16 h2 = __float2bfloat16(v.z), h3 = __float2bfloat16(v.w);
    hi[2*i]   = __nv_bfloat162(h0, h1);
    hi[2*i+1] = __nv_bfloat162(h2, h3);
    lo[2*i]   = __nv_bfloat162(__float2bfloat16(v.x - __bfloat162float(h0)),
                               __float2bfloat16(v.y - __bfloat162float(h1)));
    lo[2*i+1] = __nv_bfloat162(__float2bfloat16(v.z - __bfloat162float(h2)),
                               __float2bfloat16(v.w - __bfloat162float(h3)));
}

// Combine 64 row-block partials -> per-column rescale factors sc[by][j]
__global__ __launch_bounds__(256) void merge_kernel(
    const float* __restrict__ Mg, const float* __restrict__ Sg, float* __restrict__ sc)
{
    const int j = blockIdx.x * 256 + threadIdx.x;
    float m = -1e30f;
#pragma unroll 8
    for (int by = 0; by < 64; by++) m = fmaxf(m, Mg[(size_t)by * NPTS + j]);
    float cs = 0.f;
#pragma unroll 8
    for (int by = 0; by < 64; by++)
        cs += Sg[(size_t)by * NPTS + j] * __expf(Mg[(size_t)by * NPTS + j] - m);
    const float rcv = 1.0f / cs;
#pragma unroll 8
    for (int by = 0; by < 64; by++)
        sc[(size_t)by * NPTS + j] = __expf(Mg[(size_t)by * NPTS + j] - m) * rcv;
}

// In-place: E[i,j] *= sc[i>>7][j]  (fully normalized fp16 attention)
__global__ __launch_bounds__(256) void norm_kernel(
    __half2* __restrict__ E, const float* __restrict__ sc)
{
    const int j2 = blockIdx.x * 256 + threadIdx.x;   // half2 column index
    const int j = j2 * 2;
    const size_t i0 = (size_t)blockIdx.y * (NPTS / 16);
    for (int t = 0; t < NPTS / 16; t++) {
        const size_t i = i0 + t;
        const float* scr = sc + ((i >> 7) * (size_t)NPTS);
        const size_t idx = i * (NPTS / 2) + j2;
        float2 ef = __half22float2(E[idx]);
        E[idx] = __floats2half2_rn(ef.x * scr[j], ef.y * scr[j + 1]);
    }
}

// VT[d,j] = fp16(V[j,d])
__global__ __launch_bounds__(256) void vt_kernel(
    const float* __restrict__ V, __half* __restrict__ VT)
{
    __shared__ float t[32][33];
    const int tx = threadIdx.x, ty = threadIdx.y;
    const int d0 = blockIdx.x * 32, j0 = blockIdx.y * 32;
#pragma unroll
    for (int q = 0; q < 4; q++)
        t[ty + q * 8][tx] = V[(size_t)(j0 + ty + q * 8) * DIM + d0 + tx];
    __syncthreads();
#pragma unroll
    for (int q = 0; q < 4; q++) {
        const int d = d0 + ty + q * 8, j = j0 + tx;
        VT[(size_t)d * NPTS + j] = __float2half(t[tx][ty + q * 8]);
    }
}

extern "C" void kernel_launch(void* const* d_in, const int* in_sizes, int n_in,
                              void* d_out, int out_size)
{
    const float* p  = (const float*)d_in[0];
    const float* r  = (const float*)d_in[1];
    const float* Wh = (const float*)d_in[2];
    const float* bh = (const float*)d_in[3];
    const float* Wl = (const float*)d_in[4];
    const float* bl = (const float*)d_in[5];
    const float* Wg = (const float*)d_in[6];
    const float* bg = (const float*)d_in[7];
    float* out = (float*)d_out;

    bf16 *ph_, *pl_, *rh_, *rl_, *Whh, *Whl, *Wlh, *Wll, *Wgh, *Wgl;
    bf16 *Qh, *Ql, *Kh, *Kl;
    __half *E, *VT;
    float *V, *Mg, *Sg, *sc;
    cudaGetSymbolAddress((void**)&ph_, g_ph);  cudaGetSymbolAddress((void**)&pl_, g_pl);
    cudaGetSymbolAddress((void**)&rh_, g_rh);  cudaGetSymbolAddress((void**)&rl_, g_rl);
    cudaGetSymbolAddress((void**)&Whh, g_Whh); cudaGetSymbolAddress((void**)&Whl, g_Whl);
    cudaGetSymbolAddress((void**)&Wlh, g_Wlh); cudaGetSymbolAddress((void**)&Wll, g_Wll);
    cudaGetSymbolAddress((void**)&Wgh, g_Wgh); cudaGetSymbolAddress((void**)&Wgl, g_Wgl);
    cudaGetSymbolAddress((void**)&Qh, g_Qh);   cudaGetSymbolAddress((void**)&Ql, g_Ql);
    cudaGetSymbolAddress((void**)&Kh, g_Kh);   cudaGetSymbolAddress((void**)&Kl, g_Kl);
    cudaGetSymbolAddress((void**)&V, g_V);
    cudaGetSymbolAddress((void**)&VT, g_VT);
    cudaGetSymbolAddress((void**)&E, g_E);
    cudaGetSymbolAddress((void**)&Mg, g_M); cudaGetSymbolAddress((void**)&Sg, g_S);
    cudaGetSymbolAddress((void**)&sc, g_sc);

    cudaFuncSetAttribute(gemm_mma<0,3,0>, cudaFuncAttributeMaxDynamicSharedMemorySize, GSMEM3);
    cudaFuncSetAttribute(gemm_mma<1,3,0>, cudaFuncAttributeMaxDynamicSharedMemorySize, GSMEM3);
    cudaFuncSetAttribute(gemm_mma<2,3,0>, cudaFuncAttributeMaxDynamicSharedMemorySize, GSMEM3);
    cudaFuncSetAttribute(gemm_mma<3,1,1>, cudaFuncAttributeMaxDynamicSharedMemorySize, GSMEM1);

    const int nPD4 = NPTS * DIM / 4, nDD4 = DIM * DIM / 4;
    split_kernel<<<nPD4/256, 256>>>((const float4*)p, (__nv_bfloat162*)ph_, (__nv_bfloat162*)pl_, nPD4);
    split_kernel<<<nPD4/256, 256>>>((const float4*)r, (__nv_bfloat162*)rh_, (__nv_bfloat162*)rl_, nPD4);
    split_kernel<<<nDD4/256, 256>>>((const float4*)Wh, (__nv_bfloat162*)Whh, (__nv_bfloat162*)Whl, nDD4);
    split_kernel<<<nDD4/256, 256>>>((const float4*)Wl, (__nv_bfloat162*)Wlh, (__nv_bfloat162*)Wll, nDD4);
    split_kernel<<<nDD4/256, 256>>>((const float4*)Wg, (__nv_bfloat162*)Wgh, (__nv_bfloat162*)Wgl, nDD4);

    dim3 gproj(DIM/128, NPTS/128);
    gemm_mma<1,3,0><<<gproj, 256, GSMEM3>>>(ph_, pl_, Whh, Whl, DIM, DIM, bh, nullptr,
                                            nullptr, Qh, Ql, nullptr, nullptr);
    gemm_mma<1,3,0><<<gproj, 256, GSMEM3>>>(rh_, rl_, Wlh, Wll, DIM, DIM, bl, nullptr,
                                            nullptr, Kh, Kl, nullptr, nullptr);
    gemm_mma<0,3,0><<<gproj, 256, GSMEM3>>>(ph_, pl_, Wgh, Wgl, DIM, DIM, bg, nullptr,
                                            V, nullptr, nullptr, nullptr, nullptr);

    // Scores + tile-local softmax: E = fp16(exp(S - Mtile)), M/S partials
    dim3 gS(NPTS/128, NPTS/128);
    gemm_mma<2,3,0><<<gS, 256, GSMEM3>>>(Qh, Ql, Kh, Kl, DIM, NPTS, nullptr, nullptr,
                                         nullptr, (bf16*)E, nullptr, Mg, Sg);

    merge_kernel<<<NPTS/256, 256>>>(Mg, Sg, sc);
    norm_kernel<<<dim3(NPTS/512, 16), 256>>>((__half2*)E, sc);
    vt_kernel<<<dim3(DIM/32, NPTS/32), dim3(32, 8)>>>(V, VT);

    // Out = p + attn @ V  (fp16 x fp16, single product)
    dim3 gpv(DIM/128, NPTS/128);
    gemm_mma<3,1,1><<<gpv, 256, GSMEM1>>>((const bf16*)E, nullptr, (const bf16*)VT, nullptr,
                                          NPTS, DIM, nullptr, p, out, nullptr, nullptr,
                                          nullptr, nullptr);
}

// round 12
// speedup vs baseline: 1.1380x; 1.1380x over previous
#include <cuda_runtime.h>
#include <cuda_bf16.h>
#include <cuda_fp16.h>
#include <cstdint>
#include <cstddef>

#define NPTS 8192
#define DIM  1024
typedef __nv_bfloat16 bf16;

#define AL __align__(256)
__device__ AL bf16 g_ph[(size_t)NPTS * DIM], g_pl[(size_t)NPTS * DIM];
__device__ AL bf16 g_rh[(size_t)NPTS * DIM], g_rl[(size_t)NPTS * DIM];
__device__ AL bf16 g_Whh[(size_t)DIM * DIM], g_Whl[(size_t)DIM * DIM];
__device__ AL bf16 g_Wlh[(size_t)DIM * DIM], g_Wll[(size_t)DIM * DIM];
__device__ AL bf16 g_Wgh[(size_t)DIM * DIM], g_Wgl[(size_t)DIM * DIM];
__device__ AL bf16 g_Qh[(size_t)NPTS * DIM], g_Ql[(size_t)NPTS * DIM];
__device__ AL bf16 g_Kh[(size_t)NPTS * DIM], g_Kl[(size_t)NPTS * DIM];
__device__ AL float g_V[(size_t)NPTS * DIM];
__device__ AL __half g_VT[(size_t)DIM * NPTS];
__device__ AL __half g_E[(size_t)NPTS * NPTS];
__device__ AL float g_M[64 * NPTS];
__device__ AL float g_S[64 * NPTS];
__device__ AL float g_sc[64 * NPTS];

__device__ __forceinline__ uint32_t smem_u32(const void* p) {
    uint32_t a;
    asm("{ .reg .u64 t; cvta.to.shared.u64 t, %1; cvt.u32.u64 %0, t; }" : "=r"(a) : "l"(p));
    return a;
}
__device__ __forceinline__ void cp16(uint32_t dst, const void* src) {
    asm volatile("cp.async.cg.shared.global [%0], [%1], 16;"
                 :: "r"(dst), "l"(__cvta_generic_to_global(src)) : "memory");
}
__device__ __forceinline__ void ldmx4(uint32_t* r, uint32_t addr) {
    asm volatile("ldmatrix.sync.aligned.m8n8.x4.shared.b16 {%0,%1,%2,%3}, [%4];"
                 : "=r"(r[0]), "=r"(r[1]), "=r"(r[2]), "=r"(r[3]) : "r"(addr));
}
__device__ __forceinline__ void mma_bf(float* c, const uint32_t* a, const uint32_t* b) {
    asm volatile("mma.sync.aligned.m16n8k16.row.col.f32.bf16.bf16.f32 "
                 "{%0,%1,%2,%3}, {%4,%5,%6,%7}, {%8,%9}, {%0,%1,%2,%3};"
                 : "+f"(c[0]), "+f"(c[1]), "+f"(c[2]), "+f"(c[3])
                 : "r"(a[0]), "r"(a[1]), "r"(a[2]), "r"(a[3]), "r"(b[0]), "r"(b[1]));
}
__device__ __forceinline__ void mma_hf(float* c, const uint32_t* a, const uint32_t* b) {
    asm volatile("mma.sync.aligned.m16n8k16.row.col.f32.f16.f16.f32 "
                 "{%0,%1,%2,%3}, {%4,%5,%6,%7}, {%8,%9}, {%0,%1,%2,%3};"
                 : "+f"(c[0]), "+f"(c[1]), "+f"(c[2]), "+f"(c[3])
                 : "r"(a[0]), "r"(a[1]), "r"(a[2]), "r"(a[3]), "r"(b[0]), "r"(b[1]));
}

// CTA tile 128x128, BK=32, 3-stage cp.async. 4 warps (128 thr), warp tile 64x64.
#define BK 32
#define NSTG 3
#define GSMEM3 (3u * 32768u)
#define GSMEM1 (3u * 16384u)

__device__ __forceinline__ uint32_t swz(int row, int chunk) {
    return (uint32_t)(row * 64 + ((chunk ^ ((row >> 1) & 3)) << 4));
}

// MODE 0: bias+fp32 | 1: bias+bf16 hi/lo | 2: tile-softmax (fp16 E + M/S partials)
// MODE 3: residual fp32.  NPROD 3: hh+hl+lh | 1: hh.  HF: fp16 operands (PV).
template <int MODE, int NPROD, int HF>
__global__ __launch_bounds__(128, 2) void gemm_mma(
    const bf16* __restrict__ Ahi, const bf16* __restrict__ Alo,
    const bf16* __restrict__ Bhi, const bf16* __restrict__ Blo,
    int Kd, int ldC, const float* __restrict__ bias, const float* __restrict__ P0,
    float* __restrict__ Cf, bf16* __restrict__ Chi, bf16* __restrict__ Clo,
    float* __restrict__ Mg, float* __restrict__ Sg)
{
    constexpr uint32_t STGB   = (NPROD == 1) ? 16384u : 32768u;
    constexpr uint32_t OF_ALO = 8192u;
    constexpr uint32_t OF_BHI = (NPROD == 1) ? 8192u : 16384u;
    constexpr uint32_t OF_BLO = 24576u;

    extern __shared__ char smraw[];
    const uint32_t sm0 = smem_u32(smraw);
    const int tid = threadIdx.x, lane = tid & 31, warp = tid >> 5;
    const int wm = warp >> 1, wn = warp & 1;           // 2x2 warp grid, 64x64 tiles
    const int row0 = blockIdx.y * 128, col0 = blockIdx.x * 128;

    uint32_t aoff[4][2], boff[4][2];
#pragma unroll
    for (int mi = 0; mi < 4; mi++)
#pragma unroll
        for (int ks = 0; ks < 2; ks++) {
            const int r = wm * 64 + mi * 16 + (lane & 15);
            aoff[mi][ks] = swz(r, ks * 2 + (lane >> 4));
        }
#pragma unroll
    for (int np = 0; np < 4; np++)
#pragma unroll
        for (int ks = 0; ks < 2; ks++) {
            const int r = wn * 64 + np * 16 + (lane & 7) + ((lane >> 4) & 1) * 8;
            boff[np][ks] = swz(r, ks * 2 + ((lane >> 3) & 1));
        }

    auto load_stage = [&](int kb, int st) {
        const int k0 = kb * BK;
        const uint32_t s = sm0 + (uint32_t)st * STGB;
#pragma unroll
        for (int i = 0; i < 4; i++) {
            const int id = i * 128 + tid;
            const int row = id >> 2, chunk = id & 3;
            const uint32_t d = swz(row, chunk);
            const size_t ga = (size_t)(row0 + row) * Kd + k0 + chunk * 8;
            const size_t gb = (size_t)(col0 + row) * Kd + k0 + chunk * 8;
            cp16(s + d, Ahi + ga);
            cp16(s + OF_BHI + d, Bhi + gb);
            if (NPROD == 3) {
                cp16(s + OF_ALO + d, Alo + ga);
                cp16(s + OF_BLO + d, Blo + gb);
            }
        }
    };

    float acc[4][8][4];
#pragma unroll
    for (int mi = 0; mi < 4; mi++)
#pragma unroll
        for (int ni = 0; ni < 8; ni++)
#pragma unroll
            for (int q = 0; q < 4; q++) acc[mi][ni][q] = 0.f;

    const int nkb = Kd / BK;
    load_stage(0, 0);
    asm volatile("cp.async.commit_group;" ::: "memory");
    load_stage(1, 1);
    asm volatile("cp.async.commit_group;" ::: "memory");

    int st = 0, pf = 2;
    for (int kb = 0; kb < nkb; kb++) {
        asm volatile("cp.async.wait_group 1;" ::: "memory");
        __syncthreads();
        if (kb + 2 < nkb) load_stage(kb + 2, pf);
        asm volatile("cp.async.commit_group;" ::: "memory");

        const uint32_t s = sm0 + (uint32_t)st * STGB;
#pragma unroll
        for (int ks = 0; ks < 2; ks++) {
            uint32_t ah[4][4], al[4][4], bh[8][2], bl[8][2];
#pragma unroll
            for (int mi = 0; mi < 4; mi++) {
                ldmx4(ah[mi], s + aoff[mi][ks]);
                if (NPROD == 3) ldmx4(al[mi], s + OF_ALO + aoff[mi][ks]);
            }
#pragma unroll
            for (int np = 0; np < 4; np++) {
                uint32_t t[4];
                ldmx4(t, s + OF_BHI + boff[np][ks]);
                bh[np*2][0] = t[0]; bh[np*2][1] = t[1];
                bh[np*2+1][0] = t[2]; bh[np*2+1][1] = t[3];
                if (NPROD == 3) {
                    ldmx4(t, s + OF_BLO + boff[np][ks]);
                    bl[np*2][0] = t[0]; bl[np*2][1] = t[1];
                    bl[np*2+1][0] = t[2]; bl[np*2+1][1] = t[3];
                }
            }
#pragma unroll
            for (int mi = 0; mi < 4; mi++)
#pragma unroll
                for (int ni = 0; ni < 8; ni++) {
                    if (HF) mma_hf(acc[mi][ni], ah[mi], bh[ni]);
                    else    mma_bf(acc[mi][ni], ah[mi], bh[ni]);
                }
            if (NPROD == 3) {
#pragma unroll
                for (int mi = 0; mi < 4; mi++)
#pragma unroll
                    for (int ni = 0; ni < 8; ni++)
                        mma_bf(acc[mi][ni], ah[mi], bl[ni]);
#pragma unroll
                for (int mi = 0; mi < 4; mi++)
#pragma unroll
                    for (int ni = 0; ni < 8; ni++)
                        mma_bf(acc[mi][ni], al[mi], bh[ni]);
            }
        }
        st = (st == NSTG - 1) ? 0 : st + 1;
        pf = (pf == NSTG - 1) ? 0 : pf + 1;
    }

    if (MODE == 2) {
        // Tile-local softmax epilogue; reuse stage smem (mainloop done).
        __syncthreads();
        float* Msm  = (float*)smraw;            // [2][128]
        float* Mfin = (float*)(smraw + 1024);   // [128]
        float* Ssm  = (float*)(smraw + 1536);   // [2][128]
#pragma unroll
        for (int ni = 0; ni < 8; ni++)
#pragma unroll
            for (int cc = 0; cc < 2; cc++) {
                float v = -1e30f;
#pragma unroll
                for (int mi = 0; mi < 4; mi++)
                    v = fmaxf(v, fmaxf(acc[mi][ni][cc], acc[mi][ni][2 + cc]));
                v = fmaxf(v, __shfl_xor_sync(0xffffffffu, v, 4));
                v = fmaxf(v, __shfl_xor_sync(0xffffffffu, v, 8));
                v = fmaxf(v, __shfl_xor_sync(0xffffffffu, v, 16));
                if (lane < 4) Msm[wm * 128 + wn * 64 + ni * 8 + lane * 2 + cc] = v;
            }
        __syncthreads();
        Mfin[tid] = fmaxf(Msm[tid], Msm[128 + tid]);
        __syncthreads();
        __half* Eo = (__half*)Chi;
        float ss[8][2];
#pragma unroll
        for (int ni = 0; ni < 8; ni++) { ss[ni][0] = 0.f; ss[ni][1] = 0.f; }
#pragma unroll
        for (int mi = 0; mi < 4; mi++)
#pragma unroll
            for (int ni = 0; ni < 8; ni++) {
                const int cl = wn * 64 + ni * 8 + (lane & 3) * 2;
                const int c  = col0 + cl;
                const float M0 = Mfin[cl], M1 = Mfin[cl + 1];
#pragma unroll
                for (int h = 0; h < 2; h++) {
                    const int m = row0 + wm * 64 + mi * 16 + (lane >> 2) + h * 8;
                    float e0 = __expf(acc[mi][ni][2 * h]     - M0);
                    float e1 = __expf(acc[mi][ni][2 * h + 1] - M1);
                    *(__half2*)&Eo[(size_t)m * ldC + c] = __floats2half2_rn(e0, e1);
                    ss[ni][0] += e0; ss[ni][1] += e1;
                }
            }
#pragma unroll
        for (int ni = 0; ni < 8; ni++)
#pragma unroll
            for (int cc = 0; cc < 2; cc++) {
                float v = ss[ni][cc];
                v += __shfl_xor_sync(0xffffffffu, v, 4);
                v += __shfl_xor_sync(0xffffffffu, v, 8);
                v += __shfl_xor_sync(0xffffffffu, v, 16);
                if (lane < 4) Ssm[wm * 128 + wn * 64 + ni * 8 + lane * 2 + cc] = v;
            }
        __syncthreads();
        Mg[(size_t)blockIdx.y * ldC + col0 + tid] = Mfin[tid];
        Sg[(size_t)blockIdx.y * ldC + col0 + tid] = Ssm[tid] + Ssm[128 + tid];
        return;
    }

#pragma unroll
    for (int mi = 0; mi < 4; mi++)
#pragma unroll
        for (int ni = 0; ni < 8; ni++) {
            const int m0 = row0 + wm * 64 + mi * 16 + (lane >> 2);
            const int c  = col0 + wn * 64 + ni * 8 + (lane & 3) * 2;
#pragma unroll
            for (int h = 0; h < 2; h++) {
                const int m = m0 + h * 8;
                float v0 = acc[mi][ni][2 * h], v1 = acc[mi][ni][2 * h + 1];
                if (MODE == 0) {
                    float2* dst = (float2*)&Cf[(size_t)m * ldC + c];
                    *dst = make_float2(v0 + bias[c], v1 + bias[c + 1]);
                } else if (MODE == 3) {
                    const float2 pp = *(const float2*)&P0[(size_t)m * ldC + c];
                    float2* dst = (float2*)&Cf[(size_t)m * ldC + c];
                    *dst = make_float2(v0 + pp.x, v1 + pp.y);
                } else {  // MODE 1: bias + bf16 hi/lo split
                    v0 += bias[c]; v1 += bias[c + 1];
                    bf16 h0 = __float2bfloat16(v0), h1 = __float2bfloat16(v1);
                    *(__nv_bfloat162*)&Chi[(size_t)m * ldC + c] = __nv_bfloat162(h0, h1);
                    *(__nv_bfloat162*)&Clo[(size_t)m * ldC + c] =
                        __nv_bfloat162(__float2bfloat16(v0 - __bfloat162float(h0)),
                                       __float2bfloat16(v1 - __bfloat162float(h1)));
                }
            }
        }
}

__global__ __launch_bounds__(256) void split_kernel(
    const float4* __restrict__ x, __nv_bfloat162* __restrict__ hi,
    __nv_bfloat162* __restrict__ lo, int n4)
{
    int i = blockIdx.x * 256 + threadIdx.x;
    if (i >= n4) return;
    float4 v = x[i];
    bf16 h0 = __float2bfloat16(v.x), h1 = __float2bfloat16(v.y);
    bf16 h2 = __float2bfloat16(v.z), h3 = __float2bfloat16(v.w);
    hi[2*i]   = __nv_bfloat162(h0, h1);
    hi[2*i+1] = __nv_bfloat162(h2, h3);
    lo[2*i]   = __nv_bfloat162(__float2bfloat16(v.x - __bfloat162float(h0)),
                               __float2bfloat16(v.y - __bfloat162float(h1)));
    lo[2*i+1] = __nv_bfloat162(__float2bfloat16(v.z - __bfloat162float(h2)),
                               __float2bfloat16(v.w - __bfloat162float(h3)));
}

// Combine 64 row-block partials -> per-column rescale factors sc[by][j]
__global__ __launch_bounds__(256) void merge_kernel(
    const float* __restrict__ Mg, const float* __restrict__ Sg, float* __restrict__ sc)
{
    const int j = blockIdx.x * 256 + threadIdx.x;
    float m = -1e30f;
#pragma unroll 8
    for (int by = 0; by < 64; by++) m = fmaxf(m, Mg[(size_t)by * NPTS + j]);
    float cs = 0.f;
#pragma unroll 8
    for (int by = 0; by < 64; by++)
        cs += Sg[(size_t)by * NPTS + j] * __expf(Mg[(size_t)by * NPTS + j] - m);
    const float rcv = 1.0f / cs;
#pragma unroll 8
    for (int by = 0; by < 64; by++)
        sc[(size_t)by * NPTS + j] = __expf(Mg[(size_t)by * NPTS + j] - m) * rcv;
}

// In-place: E[i,j] *= sc[i>>7][j]
__global__ __launch_bounds__(256) void norm_kernel(
    __half2* __restrict__ E, const float* __restrict__ sc)
{
    const int j2 = blockIdx.x * 256 + threadIdx.x;
    const int j = j2 * 2;
    const size_t i0 = (size_t)blockIdx.y * (NPTS / 16);
    for (int t = 0; t < NPTS / 16; t++) {
        const size_t i = i0 + t;
        const float* scr = sc + ((i >> 7) * (size_t)NPTS);
        const size_t idx = i * (NPTS / 2) + j2;
        float2 ef = __half22float2(E[idx]);
        E[idx] = __floats2half2_rn(ef.x * scr[j], ef.y * scr[j + 1]);
    }
}

// VT[d,j] = fp16(V[j,d])
__global__ __launch_bounds__(256) void vt_kernel(
    const float* __restrict__ V, __half* __restrict__ VT)
{
    __shared__ float t[32][33];
    const int tx = threadIdx.x, ty = threadIdx.y;
    const int d0 = blockIdx.x * 32, j0 = blockIdx.y * 32;
#pragma unroll
    for (int q = 0; q < 4; q++)
        t[ty + q * 8][tx] = V[(size_t)(j0 + ty + q * 8) * DIM + d0 + tx];
    __syncthreads();
#pragma unroll
    for (int q = 0; q < 4; q++) {
        const int d = d0 + ty + q * 8, j = j0 + tx;
        VT[(size_t)d * NPTS + j] = __float2half(t[tx][ty + q * 8]);
    }
}

extern "C" void kernel_launch(void* const* d_in, const int* in_sizes, int n_in,
                              void* d_out, int out_size)
{
    const float* p  = (const float*)d_in[0];
    const float* r  = (const float*)d_in[1];
    const float* Wh = (const float*)d_in[2];
    const float* bh = (const float*)d_in[3];
    const float* Wl = (const float*)d_in[4];
    const float* bl = (const float*)d_in[5];
    const float* Wg = (const float*)d_in[6];
    const float* bg = (const float*)d_in[7];
    float* out = (float*)d_out;

    bf16 *ph_, *pl_, *rh_, *rl_, *Whh, *Whl, *Wlh, *Wll, *Wgh, *Wgl;
    bf16 *Qh, *Ql, *Kh, *Kl;
    __half *E, *VT;
    float *V, *Mg, *Sg, *sc;
    cudaGetSymbolAddress((void**)&ph_, g_ph);  cudaGetSymbolAddress((void**)&pl_, g_pl);
    cudaGetSymbolAddress((void**)&rh_, g_rh);  cudaGetSymbolAddress((void**)&rl_, g_rl);
    cudaGetSymbolAddress((void**)&Whh, g_Whh); cudaGetSymbolAddress((void**)&Whl, g_Whl);
    cudaGetSymbolAddress((void**)&Wlh, g_Wlh); cudaGetSymbolAddress((void**)&Wll, g_Wll);
    cudaGetSymbolAddress((void**)&Wgh, g_Wgh); cudaGetSymbolAddress((void**)&Wgl, g_Wgl);
    cudaGetSymbolAddress((void**)&Qh, g_Qh);   cudaGetSymbolAddress((void**)&Ql, g_Ql);
    cudaGetSymbolAddress((void**)&Kh, g_Kh);   cudaGetSymbolAddress((void**)&Kl, g_Kl);
    cudaGetSymbolAddress((void**)&V, g_V);
    cudaGetSymbolAddress((void**)&VT, g_VT);
    cudaGetSymbolAddress((void**)&E, g_E);
    cudaGetSymbolAddress((void**)&Mg, g_M); cudaGetSymbolAddress((void**)&Sg, g_S);
    cudaGetSymbolAddress((void**)&sc, g_sc);

    cudaFuncSetAttribute(gemm_mma<0,3,0>, cudaFuncAttributeMaxDynamicSharedMemorySize, GSMEM3);
    cudaFuncSetAttribute(gemm_mma<1,3,0>, cudaFuncAttributeMaxDynamicSharedMemorySize, GSMEM3);
    cudaFuncSetAttribute(gemm_mma<2,3,0>, cudaFuncAttributeMaxDynamicSharedMemorySize, GSMEM3);
    cudaFuncSetAttribute(gemm_mma<3,1,1>, cudaFuncAttributeMaxDynamicSharedMemorySize, GSMEM1);

    const int nPD4 = NPTS * DIM / 4, nDD4 = DIM * DIM / 4;
    split_kernel<<<nPD4/256, 256>>>((const float4*)p, (__nv_bfloat162*)ph_, (__nv_bfloat162*)pl_, nPD4);
    split_kernel<<<nPD4/256, 256>>>((const float4*)r, (__nv_bfloat162*)rh_, (__nv_bfloat162*)rl_, nPD4);
    split_kernel<<<nDD4/256, 256>>>((const float4*)Wh, (__nv_bfloat162*)Whh, (__nv_bfloat162*)Whl, nDD4);
    split_kernel<<<nDD4/256, 256>>>((const float4*)Wl, (__nv_bfloat162*)Wlh, (__nv_bfloat162*)Wll, nDD4);
    split_kernel<<<nDD4/256, 256>>>((const float4*)Wg, (__nv_bfloat162*)Wgh, (__nv_bfloat162*)Wgl, nDD4);

    dim3 gproj(DIM/128, NPTS/128);
    gemm_mma<1,3,0><<<gproj, 128, GSMEM3>>>(ph_, pl_, Whh, Whl, DIM, DIM, bh, nullptr,
                                            nullptr, Qh, Ql, nullptr, nullptr);
    gemm_mma<1,3,0><<<gproj, 128, GSMEM3>>>(rh_, rl_, Wlh, Wll, DIM, DIM, bl, nullptr,
                                            nullptr, Kh, Kl, nullptr, nullptr);
    gemm_mma<0,3,0><<<gproj, 128, GSMEM3>>>(ph_, pl_, Wgh, Wgl, DIM, DIM, bg, nullptr,
                                            V, nullptr, nullptr, nullptr, nullptr);

    dim3 gS(NPTS/128, NPTS/128);
    gemm_mma<2,3,0><<<gS, 128, GSMEM3>>>(Qh, Ql, Kh, Kl, DIM, NPTS, nullptr, nullptr,
                                         nullptr, (bf16*)E, nullptr, Mg, Sg);

    merge_kernel<<<NPTS/256, 256>>>(Mg, Sg, sc);
    norm_kernel<<<dim3(NPTS/512, 16), 256>>>((__half2*)E, sc);
    vt_kernel<<<dim3(DIM/32, NPTS/32), dim3(32, 8)>>>(V, VT);

    dim3 gpv(DIM/128, NPTS/128);
    gemm_mma<3,1,1><<<gpv, 128, GSMEM1>>>((const bf16*)E, nullptr, (const bf16*)VT, nullptr,
                                          NPTS, DIM, nullptr, p, out, nullptr, nullptr,
                                          nullptr, nullptr);
}

// round 13
// speedup vs baseline: 1.1445x; 1.0057x over previous
#include <cuda_runtime.h>
#include <cuda_bf16.h>
#include <cuda_fp16.h>
#include <cstdint>
#include <cstddef>

#define NPTS 8192
#define DIM  1024
typedef __nv_bfloat16 bf16;

#define AL __align__(256)
__device__ AL bf16 g_ph[(size_t)NPTS * DIM], g_pl[(size_t)NPTS * DIM];
__device__ AL bf16 g_rh[(size_t)NPTS * DIM], g_rl[(size_t)NPTS * DIM];
__device__ AL bf16 g_Whh[(size_t)DIM * DIM], g_Whl[(size_t)DIM * DIM];
__device__ AL bf16 g_Wlh[(size_t)DIM * DIM], g_Wll[(size_t)DIM * DIM];
__device__ AL bf16 g_Wgh[(size_t)DIM * DIM], g_Wgl[(size_t)DIM * DIM];
__device__ AL bf16 g_Qh[(size_t)NPTS * DIM], g_Ql[(size_t)NPTS * DIM];
__device__ AL bf16 g_Kh[(size_t)NPTS * DIM], g_Kl[(size_t)NPTS * DIM];
__device__ AL __half g_VT[(size_t)DIM * NPTS];
__device__ AL __half g_E[(size_t)NPTS * NPTS];
__device__ AL float g_M[64 * NPTS];
__device__ AL float g_S[64 * NPTS];
__device__ AL float g_sc[64 * NPTS];

__device__ __forceinline__ uint32_t smem_u32(const void* p) {
    uint32_t a;
    asm("{ .reg .u64 t; cvta.to.shared.u64 t, %1; cvt.u32.u64 %0, t; }" : "=r"(a) : "l"(p));
    return a;
}
__device__ __forceinline__ void cp16(uint32_t dst, const void* src) {
    asm volatile("cp.async.cg.shared.global [%0], [%1], 16;"
                 :: "r"(dst), "l"(__cvta_generic_to_global(src)) : "memory");
}
__device__ __forceinline__ void ldmx4(uint32_t* r, uint32_t addr) {
    asm volatile("ldmatrix.sync.aligned.m8n8.x4.shared.b16 {%0,%1,%2,%3}, [%4];"
                 : "=r"(r[0]), "=r"(r[1]), "=r"(r[2]), "=r"(r[3]) : "r"(addr));
}
__device__ __forceinline__ void mma_bf(float* c, const uint32_t* a, const uint32_t* b) {
    asm volatile("mma.sync.aligned.m16n8k16.row.col.f32.bf16.bf16.f32 "
                 "{%0,%1,%2,%3}, {%4,%5,%6,%7}, {%8,%9}, {%0,%1,%2,%3};"
                 : "+f"(c[0]), "+f"(c[1]), "+f"(c[2]), "+f"(c[3])
                 : "r"(a[0]), "r"(a[1]), "r"(a[2]), "r"(a[3]), "r"(b[0]), "r"(b[1]));
}
__device__ __forceinline__ void mma_hf(float* c, const uint32_t* a, const uint32_t* b) {
    asm volatile("mma.sync.aligned.m16n8k16.row.col.f32.f16.f16.f32 "
                 "{%0,%1,%2,%3}, {%4,%5,%6,%7}, {%8,%9}, {%0,%1,%2,%3};"
                 : "+f"(c[0]), "+f"(c[1]), "+f"(c[2]), "+f"(c[3])
                 : "r"(a[0]), "r"(a[1]), "r"(a[2]), "r"(a[3]), "r"(b[0]), "r"(b[1]));
}

// CTA tile 128x128, BK=32, cp.async pipeline (NSTGT stages). 4 warps, warp tile 64x64.
#define BK 32
#define GSMEM3 (3u * 32768u)
#define GSMEM1 (5u * 16384u)

__device__ __forceinline__ uint32_t swz(int row, int chunk) {
    return (uint32_t)(row * 64 + ((chunk ^ ((row >> 1) & 3)) << 4));
}

// MODE 0: bias+fp32 | 1: bias+bf16 hi/lo | 2: tile-softmax (fp16 E + M/S partials)
// MODE 3: residual fp32 | 4: bias + fp16 transposed (VT).  NPROD 3: hh+hl+lh | 1: hh.
template <int MODE, int NPROD, int HF, int NSTGT>
__global__ __launch_bounds__(128, 2) void gemm_mma(
    const bf16* __restrict__ Ahi, const bf16* __restrict__ Alo,
    const bf16* __restrict__ Bhi, const bf16* __restrict__ Blo,
    int Kd, int ldC, const float* __restrict__ bias, const float* __restrict__ P0,
    float* __restrict__ Cf, bf16* __restrict__ Chi, bf16* __restrict__ Clo,
    float* __restrict__ Mg, float* __restrict__ Sg)
{
    constexpr uint32_t STGB   = (NPROD == 1) ? 16384u : 32768u;
    constexpr uint32_t OF_ALO = 8192u;
    constexpr uint32_t OF_BHI = (NPROD == 1) ? 8192u : 16384u;
    constexpr uint32_t OF_BLO = 24576u;

    extern __shared__ char smraw[];
    const uint32_t sm0 = smem_u32(smraw);
    const int tid = threadIdx.x, lane = tid & 31, warp = tid >> 5;
    const int wm = warp >> 1, wn = warp & 1;           // 2x2 warp grid, 64x64 tiles
    const int row0 = blockIdx.y * 128, col0 = blockIdx.x * 128;

    uint32_t aoff[4][2], boff[4][2];
#pragma unroll
    for (int mi = 0; mi < 4; mi++)
#pragma unroll
        for (int ks = 0; ks < 2; ks++) {
            const int r = wm * 64 + mi * 16 + (lane & 15);
            aoff[mi][ks] = swz(r, ks * 2 + (lane >> 4));
        }
#pragma unroll
    for (int np = 0; np < 4; np++)
#pragma unroll
        for (int ks = 0; ks < 2; ks++) {
            const int r = wn * 64 + np * 16 + (lane & 7) + ((lane >> 4) & 1) * 8;
            boff[np][ks] = swz(r, ks * 2 + ((lane >> 3) & 1));
        }

    auto load_stage = [&](int kb, int st) {
        const int k0 = kb * BK;
        const uint32_t s = sm0 + (uint32_t)st * STGB;
#pragma unroll
        for (int i = 0; i < 4; i++) {
            const int id = i * 128 + tid;
            const int row = id >> 2, chunk = id & 3;
            const uint32_t d = swz(row, chunk);
            const size_t ga = (size_t)(row0 + row) * Kd + k0 + chunk * 8;
            const size_t gb = (size_t)(col0 + row) * Kd + k0 + chunk * 8;
            cp16(s + d, Ahi + ga);
            cp16(s + OF_BHI + d, Bhi + gb);
            if (NPROD == 3) {
                cp16(s + OF_ALO + d, Alo + ga);
                cp16(s + OF_BLO + d, Blo + gb);
            }
        }
    };

    float acc[4][8][4];
#pragma unroll
    for (int mi = 0; mi < 4; mi++)
#pragma unroll
        for (int ni = 0; ni < 8; ni++)
#pragma unroll
            for (int q = 0; q < 4; q++) acc[mi][ni][q] = 0.f;

    const int nkb = Kd / BK;
#pragma unroll
    for (int s = 0; s < NSTGT - 1; s++) {
        load_stage(s, s);
        asm volatile("cp.async.commit_group;" ::: "memory");
    }

    int st = 0, pf = NSTGT - 1;
    for (int kb = 0; kb < nkb; kb++) {
        asm volatile("cp.async.wait_group %0;" :: "n"(NSTGT - 2) : "memory");
        __syncthreads();
        if (kb + NSTGT - 1 < nkb) load_stage(kb + NSTGT - 1, pf);
        asm volatile("cp.async.commit_group;" ::: "memory");

        const uint32_t s = sm0 + (uint32_t)st * STGB;
#pragma unroll
        for (int ks = 0; ks < 2; ks++) {
            uint32_t ah[4][4], al[4][4], bh[8][2], bl[8][2];
#pragma unroll
            for (int mi = 0; mi < 4; mi++) {
                ldmx4(ah[mi], s + aoff[mi][ks]);
                if (NPROD == 3) ldmx4(al[mi], s + OF_ALO + aoff[mi][ks]);
            }
#pragma unroll
            for (int np = 0; np < 4; np++) {
                uint32_t t[4];
                ldmx4(t, s + OF_BHI + boff[np][ks]);
                bh[np*2][0] = t[0]; bh[np*2][1] = t[1];
                bh[np*2+1][0] = t[2]; bh[np*2+1][1] = t[3];
                if (NPROD == 3) {
                    ldmx4(t, s + OF_BLO + boff[np][ks]);
                    bl[np*2][0] = t[0]; bl[np*2][1] = t[1];
                    bl[np*2+1][0] = t[2]; bl[np*2+1][1] = t[3];
                }
            }
#pragma unroll
            for (int mi = 0; mi < 4; mi++)
#pragma unroll
                for (int ni = 0; ni < 8; ni++) {
                    if (HF) mma_hf(acc[mi][ni], ah[mi], bh[ni]);
                    else    mma_bf(acc[mi][ni], ah[mi], bh[ni]);
                }
            if (NPROD == 3) {
#pragma unroll
                for (int mi = 0; mi < 4; mi++)
#pragma unroll
                    for (int ni = 0; ni < 8; ni++)
                        mma_bf(acc[mi][ni], ah[mi], bl[ni]);
#pragma unroll
                for (int mi = 0; mi < 4; mi++)
#pragma unroll
                    for (int ni = 0; ni < 8; ni++)
                        mma_bf(acc[mi][ni], al[mi], bh[ni]);
            }
        }
        st = (st == NSTGT - 1) ? 0 : st + 1;
        pf = (pf == NSTGT - 1) ? 0 : pf + 1;
    }

    if (MODE == 2) {
        // Tile-local softmax epilogue; reuse stage smem (mainloop done).
        __syncthreads();
        float* Msm  = (float*)smraw;            // [2][128]
        float* Mfin = (float*)(smraw + 1024);   // [128]
        float* Ssm  = (float*)(smraw + 1536);   // [2][128]
#pragma unroll
        for (int ni = 0; ni < 8; ni++)
#pragma unroll
            for (int cc = 0; cc < 2; cc++) {
                float v = -1e30f;
#pragma unroll
                for (int mi = 0; mi < 4; mi++)
                    v = fmaxf(v, fmaxf(acc[mi][ni][cc], acc[mi][ni][2 + cc]));
                v = fmaxf(v, __shfl_xor_sync(0xffffffffu, v, 4));
                v = fmaxf(v, __shfl_xor_sync(0xffffffffu, v, 8));
                v = fmaxf(v, __shfl_xor_sync(0xffffffffu, v, 16));
                if (lane < 4) Msm[wm * 128 + wn * 64 + ni * 8 + lane * 2 + cc] = v;
            }
        __syncthreads();
        Mfin[tid] = fmaxf(Msm[tid], Msm[128 + tid]);
        __syncthreads();
        __half* Eo = (__half*)Chi;
        const float L2E = 1.4426950408889634f;
        float ss[8][2];
#pragma unroll
        for (int ni = 0; ni < 8; ni++) { ss[ni][0] = 0.f; ss[ni][1] = 0.f; }
#pragma unroll
        for (int mi = 0; mi < 4; mi++)
#pragma unroll
            for (int ni = 0; ni < 8; ni++) {
                const int cl = wn * 64 + ni * 8 + (lane & 3) * 2;
                const int c  = col0 + cl;
                const float M0 = Mfin[cl], M1 = Mfin[cl + 1];
#pragma unroll
                for (int h = 0; h < 2; h++) {
                    const int m = row0 + wm * 64 + mi * 16 + (lane >> 2) + h * 8;
                    // exp via single f16x2 MUFU: e = 2^((S-M)*log2e)
                    float t0 = (acc[mi][ni][2 * h]     - M0) * L2E;
                    float t1 = (acc[mi][ni][2 * h + 1] - M1) * L2E;
                    __half2 ht = __floats2half2_rn(t0, t1);
                    uint32_t hin = *(uint32_t*)&ht, ho;
                    asm("ex2.approx.f16x2 %0, %1;" : "=r"(ho) : "r"(hin));
                    __half2 he = *(__half2*)&ho;
                    *(__half2*)&Eo[(size_t)m * ldC + c] = he;
                    float2 ef = __half22float2(he);
                    ss[ni][0] += ef.x; ss[ni][1] += ef.y;
                }
            }
#pragma unroll
        for (int ni = 0; ni < 8; ni++)
#pragma unroll
            for (int cc = 0; cc < 2; cc++) {
                float v = ss[ni][cc];
                v += __shfl_xor_sync(0xffffffffu, v, 4);
                v += __shfl_xor_sync(0xffffffffu, v, 8);
                v += __shfl_xor_sync(0xffffffffu, v, 16);
                if (lane < 4) Ssm[wm * 128 + wn * 64 + ni * 8 + lane * 2 + cc] = v;
            }
        __syncthreads();
        Mg[(size_t)blockIdx.y * ldC + col0 + tid] = Mfin[tid];
        Sg[(size_t)blockIdx.y * ldC + col0 + tid] = Ssm[tid] + Ssm[128 + tid];
        return;
    }

#pragma unroll
    for (int mi = 0; mi < 4; mi++)
#pragma unroll
        for (int ni = 0; ni < 8; ni++) {
            const int m0 = row0 + wm * 64 + mi * 16 + (lane >> 2);
            const int c  = col0 + wn * 64 + ni * 8 + (lane & 3) * 2;
#pragma unroll
            for (int h = 0; h < 2; h++) {
                const int m = m0 + h * 8;
                float v0 = acc[mi][ni][2 * h], v1 = acc[mi][ni][2 * h + 1];
                if (MODE == 0) {
                    float2* dst = (float2*)&Cf[(size_t)m * ldC + c];
                    *dst = make_float2(v0 + bias[c], v1 + bias[c + 1]);
                } else if (MODE == 3) {
                    const float2 pp = *(const float2*)&P0[(size_t)m * ldC + c];
                    float2* dst = (float2*)&Cf[(size_t)m * ldC + c];
                    *dst = make_float2(v0 + pp.x, v1 + pp.y);
                } else if (MODE == 4) {
                    // V projection -> fp16 transposed VT[d][j], d=c, j=m
                    __half* VTo = (__half*)Chi;
                    VTo[(size_t)c       * NPTS + m] = __float2half(v0 + bias[c]);
                    VTo[(size_t)(c + 1) * NPTS + m] = __float2half(v1 + bias[c + 1]);
                } else {  // MODE 1: bias + bf16 hi/lo split
                    v0 += bias[c]; v1 += bias[c + 1];
                    bf16 h0 = __float2bfloat16(v0), h1 = __float2bfloat16(v1);
                    *(__nv_bfloat162*)&Chi[(size_t)m * ldC + c] = __nv_bfloat162(h0, h1);
                    *(__nv_bfloat162*)&Clo[(size_t)m * ldC + c] =
                        __nv_bfloat162(__float2bfloat16(v0 - __bfloat162float(h0)),
                                       __float2bfloat16(v1 - __bfloat162float(h1)));
                }
            }
        }
}

__global__ __launch_bounds__(256) void split_kernel(
    const float4* __restrict__ x, __nv_bfloat162* __restrict__ hi,
    __nv_bfloat162* __restrict__ lo, int n4)
{
    int i = blockIdx.x * 256 + threadIdx.x;
    if (i >= n4) return;
    float4 v = x[i];
    bf16 h0 = __float2bfloat16(v.x), h1 = __float2bfloat16(v.y);
    bf16 h2 = __float2bfloat16(v.z), h3 = __float2bfloat16(v.w);
    hi[2*i]   = __nv_bfloat162(h0, h1);
    hi[2*i+1] = __nv_bfloat162(h2, h3);
    lo[2*i]   = __nv_bfloat162(__float2bfloat16(v.x - __bfloat162float(h0)),
                               __float2bfloat16(v.y - __bfloat162float(h1)));
    lo[2*i+1] = __nv_bfloat162(__float2bfloat16(v.z - __bfloat162float(h2)),
                               __float2bfloat16(v.w - __bfloat162float(h3)));
}

// Combine 64 row-block partials -> per-column rescale factors sc[by][j]
__global__ __launch_bounds__(256) void merge_kernel(
    const float* __restrict__ Mg, const float* __restrict__ Sg, float* __restrict__ sc)
{
    const int j = blockIdx.x * 256 + threadIdx.x;
    float m = -1e30f;
#pragma unroll 8
    for (int by = 0; by < 64; by++) m = fmaxf(m, Mg[(size_t)by * NPTS + j]);
    float cs = 0.f;
#pragma unroll 8
    for (int by = 0; by < 64; by++)
        cs += Sg[(size_t)by * NPTS + j] * __expf(Mg[(size_t)by * NPTS + j] - m);
    const float rcv = 1.0f / cs;
#pragma unroll 8
    for (int by = 0; by < 64; by++)
        sc[(size_t)by * NPTS + j] = __expf(Mg[(size_t)by * NPTS + j] - m) * rcv;
}

// In-place: E[i,j] *= sc[i>>7][j]
__global__ __launch_bounds__(256) void norm_kernel(
    __half2* __restrict__ E, const float* __restrict__ sc)
{
    const int j2 = blockIdx.x * 256 + threadIdx.x;
    const int j = j2 * 2;
    const size_t i0 = (size_t)blockIdx.y * (NPTS / 16);
    for (int t = 0; t < NPTS / 16; t++) {
        const size_t i = i0 + t;
        const float* scr = sc + ((i >> 7) * (size_t)NPTS);
        const size_t idx = i * (NPTS / 2) + j2;
        float2 ef = __half22float2(E[idx]);
        E[idx] = __floats2half2_rn(ef.x * scr[j], ef.y * scr[j + 1]);
    }
}

extern "C" void kernel_launch(void* const* d_in, const int* in_sizes, int n_in,
                              void* d_out, int out_size)
{
    const float* p  = (const float*)d_in[0];
    const float* r  = (const float*)d_in[1];
    const float* Wh = (const float*)d_in[2];
    const float* bh = (const float*)d_in[3];
    const float* Wl = (const float*)d_in[4];
    const float* bl = (const float*)d_in[5];
    const float* Wg = (const float*)d_in[6];
    const float* bg = (const float*)d_in[7];
    float* out = (float*)d_out;

    bf16 *ph_, *pl_, *rh_, *rl_, *Whh, *Whl, *Wlh, *Wll, *Wgh, *Wgl;
    bf16 *Qh, *Ql, *Kh, *Kl;
    __half *E, *VT;
    float *Mg, *Sg, *sc;
    cudaGetSymbolAddress((void**)&ph_, g_ph);  cudaGetSymbolAddress((void**)&pl_, g_pl);
    cudaGetSymbolAddress((void**)&rh_, g_rh);  cudaGetSymbolAddress((void**)&rl_, g_rl);
    cudaGetSymbolAddress((void**)&Whh, g_Whh); cudaGetSymbolAddress((void**)&Whl, g_Whl);
    cudaGetSymbolAddress((void**)&Wlh, g_Wlh); cudaGetSymbolAddress((void**)&Wll, g_Wll);
    cudaGetSymbolAddress((void**)&Wgh, g_Wgh); cudaGetSymbolAddress((void**)&Wgl, g_Wgl);
    cudaGetSymbolAddress((void**)&Qh, g_Qh);   cudaGetSymbolAddress((void**)&Ql, g_Ql);
    cudaGetSymbolAddress((void**)&Kh, g_Kh);   cudaGetSymbolAddress((void**)&Kl, g_Kl);
    cudaGetSymbolAddress((void**)&VT, g_VT);
    cudaGetSymbolAddress((void**)&E, g_E);
    cudaGetSymbolAddress((void**)&Mg, g_M); cudaGetSymbolAddress((void**)&Sg, g_S);
    cudaGetSymbolAddress((void**)&sc, g_sc);

    cudaFuncSetAttribute(gemm_mma<1,3,0,3>, cudaFuncAttributeMaxDynamicSharedMemorySize, GSMEM3);
    cudaFuncSetAttribute(gemm_mma<4,3,0,3>, cudaFuncAttributeMaxDynamicSharedMemorySize, GSMEM3);
    cudaFuncSetAttribute(gemm_mma<2,3,0,3>, cudaFuncAttributeMaxDynamicSharedMemorySize, GSMEM3);
    cudaFuncSetAttribute(gemm_mma<3,1,1,5>, cudaFuncAttributeMaxDynamicSharedMemorySize, GSMEM1);

    const int nPD4 = NPTS * DIM / 4, nDD4 = DIM * DIM / 4;
    split_kernel<<<nPD4/256, 256>>>((const float4*)p, (__nv_bfloat162*)ph_, (__nv_bfloat162*)pl_, nPD4);
    split_kernel<<<nPD4/256, 256>>>((const float4*)r, (__nv_bfloat162*)rh_, (__nv_bfloat162*)rl_, nPD4);
    split_kernel<<<nDD4/256, 256>>>((const float4*)Wh, (__nv_bfloat162*)Whh, (__nv_bfloat162*)Whl, nDD4);
    split_kernel<<<nDD4/256, 256>>>((const float4*)Wl, (__nv_bfloat162*)Wlh, (__nv_bfloat162*)Wll, nDD4);
    split_kernel<<<nDD4/256, 256>>>((const float4*)Wg, (__nv_bfloat162*)Wgh, (__nv_bfloat162*)Wgl, nDD4);

    dim3 gproj(DIM/128, NPTS/128);
    gemm_mma<1,3,0,3><<<gproj, 128, GSMEM3>>>(ph_, pl_, Whh, Whl, DIM, DIM, bh, nullptr,
                                              nullptr, Qh, Ql, nullptr, nullptr);
    gemm_mma<1,3,0,3><<<gproj, 128, GSMEM3>>>(rh_, rl_, Wlh, Wll, DIM, DIM, bl, nullptr,
                                              nullptr, Kh, Kl, nullptr, nullptr);
    // V projection writes fp16 transposed VT directly (vt kernel fused away)
    gemm_mma<4,3,0,3><<<gproj, 128, GSMEM3>>>(ph_, pl_, Wgh, Wgl, DIM, DIM, bg, nullptr,
                                              nullptr, (bf16*)VT, nullptr, nullptr, nullptr);

    dim3 gS(NPTS/128, NPTS/128);
    gemm_mma<2,3,0,3><<<gS, 128, GSMEM3>>>(Qh, Ql, Kh, Kl, DIM, NPTS, nullptr, nullptr,
                                           nullptr, (bf16*)E, nullptr, Mg, Sg);

    merge_kernel<<<NPTS/256, 256>>>(Mg, Sg, sc);
    norm_kernel<<<dim3(NPTS/512, 16), 256>>>((__half2*)E, sc);

    dim3 gpv(DIM/128, NPTS/128);
    gemm_mma<3,1,1,5><<<gpv, 128, GSMEM1>>>((const bf16*)E, nullptr, (const bf16*)VT, nullptr,
                                            NPTS, DIM, nullptr, p, out, nullptr, nullptr,
                                            nullptr, nullptr);
}